// round 14
// baseline (speedup 1.0000x reference)
#include <cuda_runtime.h>
#include <cstdint>
#include <math.h>

#define HDIM 1024
#define FDIM 2048
#define NEXP 8
#define NGRP 9
#define NTOK 4096
#define NROWS_ROUTED 8192
#define NROWS_TOTAL 12288

typedef unsigned long long u64;

// ---------------- scratch (static device globals; no allocation) ----------------
__device__ __align__(256) float g_act[(size_t)NROWS_TOTAL * FDIM];  // silu(gate)*up
__device__ __align__(256) float g_y[(size_t)NROWS_TOTAL * HDIM];    // down outputs
__device__ __align__(256) float g_probs[(size_t)NTOK * NEXP];       // router softmax probs
__device__ __align__(256) float g_zsq[NTOK];                        // z^2 per token
__device__ int   g_rowtok[NROWS_TOTAL];
__device__ int   g_tokpos[NTOK * 2];
__device__ float g_tokw[NTOK * 2];
__device__ float g_imp[NEXP];
__device__ int   g_load[NEXP];
__device__ float g_z2;
__device__ int   g_cnt[NEXP];
__device__ int   g_off[NEXP];
__device__ int   g_cur[NEXP];

// ---------------- packed f32x2 helpers ----------------
__device__ __forceinline__ u64 pack2(float x, float y) {
    u64 r; asm("mov.b64 %0, {%1, %2};" : "=l"(r) : "f"(x), "f"(y)); return r;
}
__device__ __forceinline__ u64 ffma2(u64 a, u64 b, u64 c) {
    u64 d; asm("fma.rn.f32x2 %0, %1, %2, %3;" : "=l"(d) : "l"(a), "l"(b), "l"(c)); return d;
}
__device__ __forceinline__ float2 unpack2(u64 v) {
    float2 f; asm("mov.b64 {%0, %1}, %2;" : "=f"(f.x), "=f"(f.y) : "l"(v)); return f;
}

// ---------------- router: logits, softmax, top-2 (no global atomics) ----------------
__global__ void router_kernel(const float* __restrict__ x, const float* __restrict__ wr) {
    int n = blockIdx.x;
    int tid = threadIdx.x;
    int w = tid >> 5, lane = tid & 31;
    const float* xr = x + (size_t)n * HDIM;
    const float* we = wr + (size_t)w * HDIM;
    float s = 0.f;
    for (int j = lane; j < HDIM; j += 32) s += xr[j] * we[j];
    #pragma unroll
    for (int o = 16; o; o >>= 1) s += __shfl_xor_sync(0xffffffffu, s, o);
    __shared__ float lg[NEXP];
    if (lane == 0) lg[w] = s;
    __syncthreads();
    if (tid == 0) {
        float l[NEXP], p[NEXP];
        float m = -1e30f;
        #pragma unroll
        for (int e = 0; e < NEXP; e++) { l[e] = lg[e]; m = fmaxf(m, l[e]); }
        float se = 0.f;
        #pragma unroll
        for (int e = 0; e < NEXP; e++) { p[e] = expf(l[e] - m); se += p[e]; }
        float inv = 1.f / se;
        #pragma unroll
        for (int e = 0; e < NEXP; e++) { p[e] *= inv; g_probs[(size_t)n * NEXP + e] = p[e]; }
        float z = m + logf(se);
        g_zsq[n] = z * z;
        // top-2, first-occurrence tie-break (matches jax.lax.top_k)
        int i1 = 0;
        #pragma unroll
        for (int e = 1; e < NEXP; e++) if (p[e] > p[i1]) i1 = e;
        int i2 = -1;
        #pragma unroll
        for (int e = 0; e < NEXP; e++) {
            if (e == i1) continue;
            if (i2 < 0 || p[e] > p[i2]) i2 = e;
        }
        float denom = p[i1] + p[i2] + 1e-9f;
        g_tokw[n * 2 + 0] = p[i1] / denom;
        g_tokw[n * 2 + 1] = p[i2] / denom;
        g_tokpos[n * 2 + 0] = i1;
        g_tokpos[n * 2 + 1] = i2;
    }
}

// ---------------- reduce + prefix: cnt/load/importance/z2 + offsets ----------------
__global__ void reduce_prefix_kernel() {
    __shared__ int scnt[NEXP], sload[NEXP];
    __shared__ float simp[NEXP], sz2;
    int tid = threadIdx.x;
    if (tid < NEXP) { scnt[tid] = 0; sload[tid] = 0; simp[tid] = 0.f; }
    if (tid == NEXP) sz2 = 0.f;
    __syncthreads();

    float limp[NEXP];
    #pragma unroll
    for (int e = 0; e < NEXP; e++) limp[e] = 0.f;
    float lz2 = 0.f;
    int lcnt[NEXP], lload[NEXP];
    #pragma unroll
    for (int e = 0; e < NEXP; e++) { lcnt[e] = 0; lload[e] = 0; }

    for (int n = tid; n < NTOK; n += blockDim.x) {
        int i1 = g_tokpos[n * 2], i2 = g_tokpos[n * 2 + 1];
        lcnt[i1]++; lcnt[i2]++; lload[i1]++;
        #pragma unroll
        for (int e = 0; e < NEXP; e++) limp[e] += g_probs[(size_t)n * NEXP + e];
        lz2 += g_zsq[n];
    }
    #pragma unroll
    for (int e = 0; e < NEXP; e++) {
        if (lcnt[e])  atomicAdd(&scnt[e], lcnt[e]);
        if (lload[e]) atomicAdd(&sload[e], lload[e]);
        atomicAdd(&simp[e], limp[e]);
    }
    atomicAdd(&sz2, lz2);
    __syncthreads();

    if (tid == 0) {
        int o = 0;
        for (int e = 0; e < NEXP; e++) {
            g_cnt[e] = scnt[e]; g_load[e] = sload[e]; g_imp[e] = simp[e];
            g_off[e] = o; o += scnt[e]; g_cur[e] = 0;
        }
        g_z2 = sz2;
    }
}

__global__ void scatter_kernel() {
    int n = blockIdx.x * blockDim.x + threadIdx.x;
    if (n < NTOK) {
        #pragma unroll
        for (int k = 0; k < 2; k++) {
            int e = g_tokpos[n * 2 + k];
            int p = g_off[e] + atomicAdd(&g_cur[e], 1);
            g_rowtok[p] = n;
            g_tokpos[n * 2 + k] = p;
        }
        g_rowtok[NROWS_ROUTED + n] = n; // shared-expert group rows
    }
}

// ---------------- grouped GEMMs (FFMA2), B-tile register prefetch ----------------
#define BM 128
#define BN 64
#define BK 16

// Fused gate+up: act[r][f] = silu(A[r].Wg[e][f]) * (A[r].Wu[e][f]), K = HDIM
__global__ void __launch_bounds__(256, 2)
gemm_gu_kernel(const float* __restrict__ x,
               const float* __restrict__ weg, const float* __restrict__ wshg,
               const float* __restrict__ weu, const float* __restrict__ wshu) {
    const int g = blockIdx.y;
    int off, cnt;
    if (g < NEXP) { off = g_off[g]; cnt = g_cnt[g]; }
    else          { off = NROWS_ROUTED; cnt = NTOK; }
    const int row0 = blockIdx.x * BM;
    if (row0 >= cnt) return;

    const float* Bg = (g < NEXP) ? (weg + (size_t)g * ((size_t)FDIM * HDIM)) : wshg;
    const float* Bu = (g < NEXP) ? (weu + (size_t)g * ((size_t)FDIM * HDIM)) : wshu;
    const int n0 = blockIdx.z * BN;

    __shared__ float As [BK][BM + 4];
    __shared__ float Bgs[BK][BN + 4];
    __shared__ float Bus[BK][BN + 4];
    __shared__ const float* Arow[BM];

    const int tid = threadIdx.x;
    if (tid < BM) {
        int r = row0 + tid;
        int rc = (r < cnt) ? r : (cnt - 1);
        Arow[tid] = x + (size_t)g_rowtok[off + rc] * HDIM;
    }
    __syncthreads();

    u64 accg[8][2], accu[8][2];
    #pragma unroll
    for (int i = 0; i < 8; i++) { accg[i][0] = accg[i][1] = 0ull; accu[i][0] = accu[i][1] = 0ull; }

    const int tr = tid >> 4, tc = tid & 15;
    const int lm = tid >> 2, lk = tid & 3;      // A-load: row lm, k-quad lk
    const int bn = tid >> 2, bk = tid & 3;      // B-load: col bn, k-quad bk

    const float* aptr0 = Arow[lm]      + lk * 4;
    const float* aptr1 = Arow[lm + 64] + lk * 4;
    const float* bgp = Bg + (size_t)(n0 + bn) * HDIM + bk * 4;
    const float* bup = Bu + (size_t)(n0 + bn) * HDIM + bk * 4;

    // prefetch first B tiles (weights stream from DRAM; x-rows stay L2-hot)
    float4 pg = *(const float4*)(bgp);
    float4 pu = *(const float4*)(bup);

    for (int kt = 0; kt < HDIM; kt += BK) {
        {
            float4 v = *(const float4*)(aptr0 + kt);
            As[lk * 4 + 0][lm] = v.x; As[lk * 4 + 1][lm] = v.y;
            As[lk * 4 + 2][lm] = v.z; As[lk * 4 + 3][lm] = v.w;
            float4 w = *(const float4*)(aptr1 + kt);
            As[lk * 4 + 0][lm + 64] = w.x; As[lk * 4 + 1][lm + 64] = w.y;
            As[lk * 4 + 2][lm + 64] = w.z; As[lk * 4 + 3][lm + 64] = w.w;
            Bgs[bk * 4 + 0][bn] = pg.x; Bgs[bk * 4 + 1][bn] = pg.y;
            Bgs[bk * 4 + 2][bn] = pg.z; Bgs[bk * 4 + 3][bn] = pg.w;
            Bus[bk * 4 + 0][bn] = pu.x; Bus[bk * 4 + 1][bn] = pu.y;
            Bus[bk * 4 + 2][bn] = pu.z; Bus[bk * 4 + 3][bn] = pu.w;
        }
        __syncthreads();
        if (kt + BK < HDIM) {   // issue next B loads; latency overlapped by compute
            pg = *(const float4*)(bgp + kt + BK);
            pu = *(const float4*)(bup + kt + BK);
        }
        #pragma unroll
        for (int kk = 0; kk < BK; kk++) {
            float4 a0 = *(const float4*)&As[kk][tr * 8];
            float4 a1 = *(const float4*)&As[kk][tr * 8 + 4];
            ulonglong2 bg2 = *(const ulonglong2*)&Bgs[kk][tc * 4];
            ulonglong2 bu2 = *(const ulonglong2*)&Bus[kk][tc * 4];
            u64 a2[8];
            a2[0] = pack2(a0.x, a0.x); a2[1] = pack2(a0.y, a0.y);
            a2[2] = pack2(a0.z, a0.z); a2[3] = pack2(a0.w, a0.w);
            a2[4] = pack2(a1.x, a1.x); a2[5] = pack2(a1.y, a1.y);
            a2[6] = pack2(a1.z, a1.z); a2[7] = pack2(a1.w, a1.w);
            #pragma unroll
            for (int i = 0; i < 8; i++) {
                accg[i][0] = ffma2(a2[i], bg2.x, accg[i][0]);
                accg[i][1] = ffma2(a2[i], bg2.y, accg[i][1]);
                accu[i][0] = ffma2(a2[i], bu2.x, accu[i][0]);
                accu[i][1] = ffma2(a2[i], bu2.y, accu[i][1]);
            }
        }
        __syncthreads();
    }

    #pragma unroll
    for (int i = 0; i < 8; i++) {
        int r = row0 + tr * 8 + i;
        if (r < cnt) {
            float* o = g_act + (size_t)(off + r) * FDIM + n0 + tc * 4;
            #pragma unroll
            for (int jp = 0; jp < 2; jp++) {
                float2 gg = unpack2(accg[i][jp]);
                float2 uu = unpack2(accu[i][jp]);
                o[jp * 2 + 0] = (gg.x / (1.f + __expf(-gg.x))) * uu.x;
                o[jp * 2 + 1] = (gg.y / (1.f + __expf(-gg.y))) * uu.y;
            }
        }
    }
}

// Down: y[r][h] = act[r] . Wd[e][h], K = FDIM. Prefetch A and B.
__global__ void __launch_bounds__(256, 2)
gemm_down_kernel(const float* __restrict__ wed, const float* __restrict__ wshd) {
    const int g = blockIdx.y;
    int off, cnt;
    if (g < NEXP) { off = g_off[g]; cnt = g_cnt[g]; }
    else          { off = NROWS_ROUTED; cnt = NTOK; }
    const int row0 = blockIdx.x * BM;
    if (row0 >= cnt) return;

    const float* Bp = (g < NEXP) ? (wed + (size_t)g * ((size_t)HDIM * FDIM)) : wshd;
    const int n0 = blockIdx.z * BN;

    __shared__ float As[BK][BM + 4];
    __shared__ float Bs[BK][BN + 4];

    const int tid = threadIdx.x;
    const int tr = tid >> 4, tc = tid & 15;
    const int lm = tid >> 2, lk = tid & 3;
    const int bn = tid >> 2, bk = tid & 3;

    const int rA  = (row0 + lm      < cnt) ? (row0 + lm)      : (cnt - 1);
    const int rA1 = (row0 + lm + 64 < cnt) ? (row0 + lm + 64) : (cnt - 1);
    const float* a_base0 = g_act + (size_t)(off + rA)  * FDIM + lk * 4;
    const float* a_base1 = g_act + (size_t)(off + rA1) * FDIM + lk * 4;
    const float* b_base  = Bp + (size_t)(n0 + bn) * FDIM + bk * 4;

    u64 acc[8][2];
    #pragma unroll
    for (int i = 0; i < 8; i++) { acc[i][0] = 0ull; acc[i][1] = 0ull; }

    float4 p0 = *(const float4*)(a_base0);
    float4 p1 = *(const float4*)(a_base1);
    float4 pb = *(const float4*)(b_base);

    for (int kt = 0; kt < FDIM; kt += BK) {
        {
            As[lk * 4 + 0][lm] = p0.x; As[lk * 4 + 1][lm] = p0.y;
            As[lk * 4 + 2][lm] = p0.z; As[lk * 4 + 3][lm] = p0.w;
            As[lk * 4 + 0][lm + 64] = p1.x; As[lk * 4 + 1][lm + 64] = p1.y;
            As[lk * 4 + 2][lm + 64] = p1.z; As[lk * 4 + 3][lm + 64] = p1.w;
            Bs[bk * 4 + 0][bn] = pb.x; Bs[bk * 4 + 1][bn] = pb.y;
            Bs[bk * 4 + 2][bn] = pb.z; Bs[bk * 4 + 3][bn] = pb.w;
        }
        __syncthreads();
        if (kt + BK < FDIM) {
            p0 = *(const float4*)(a_base0 + kt + BK);
            p1 = *(const float4*)(a_base1 + kt + BK);
            pb = *(const float4*)(b_base + kt + BK);
        }
        #pragma unroll
        for (int kk = 0; kk < BK; kk++) {
            float4 a0 = *(const float4*)&As[kk][tr * 8];
            float4 a1 = *(const float4*)&As[kk][tr * 8 + 4];
            ulonglong2 b2 = *(const ulonglong2*)&Bs[kk][tc * 4];
            u64 a2[8];
            a2[0] = pack2(a0.x, a0.x); a2[1] = pack2(a0.y, a0.y);
            a2[2] = pack2(a0.z, a0.z); a2[3] = pack2(a0.w, a0.w);
            a2[4] = pack2(a1.x, a1.x); a2[5] = pack2(a1.y, a1.y);
            a2[6] = pack2(a1.z, a1.z); a2[7] = pack2(a1.w, a1.w);
            #pragma unroll
            for (int i = 0; i < 8; i++) {
                acc[i][0] = ffma2(a2[i], b2.x, acc[i][0]);
                acc[i][1] = ffma2(a2[i], b2.y, acc[i][1]);
            }
        }
        __syncthreads();
    }

    #pragma unroll
    for (int i = 0; i < 8; i++) {
        int r = row0 + tr * 8 + i;
        if (r < cnt) {
            float* o = g_y + (size_t)(off + r) * HDIM + n0 + tc * 4;
            float2 v0 = unpack2(acc[i][0]);
            float2 v1 = unpack2(acc[i][1]);
            o[0] = v0.x; o[1] = v0.y; o[2] = v1.x; o[3] = v1.y;
        }
    }
}

// ---------------- combine: y = shared + w0*e0 + w1*e1 ----------------
__global__ void combine_kernel(float* __restrict__ out) {
    int n = blockIdx.x;
    int p0 = g_tokpos[n * 2], p1 = g_tokpos[n * 2 + 1];
    float w0 = g_tokw[n * 2], w1 = g_tokw[n * 2 + 1];
    const float4* ysh = (const float4*)(g_y + (size_t)(NROWS_ROUTED + n) * HDIM);
    const float4* y0  = (const float4*)(g_y + (size_t)p0 * HDIM);
    const float4* y1  = (const float4*)(g_y + (size_t)p1 * HDIM);
    float4* o = (float4*)(out + (size_t)n * HDIM);
    for (int h = threadIdx.x; h < HDIM / 4; h += blockDim.x) {
        float4 s = ysh[h], a = y0[h], b = y1[h], rr;
        rr.x = s.x + w0 * a.x + w1 * b.x;
        rr.y = s.y + w0 * a.y + w1 * b.y;
        rr.z = s.z + w0 * a.z + w1 * b.z;
        rr.w = s.w + w0 * a.w + w1 * b.w;
        o[h] = rr;
    }
}

// ---------------- aux losses ----------------
__global__ void aux_kernel(float* __restrict__ out, int out_size) {
    const int yelems = NTOK * HDIM;
    if (out_size <= yelems) return;
    float imp[NEXP], ld[NEXP];
    float impSum = 0.f, loadSum = 0.f;
    for (int e = 0; e < NEXP; e++) {
        imp[e] = g_imp[e]; ld[e] = (float)g_load[e];
        impSum += imp[e]; loadSum += ld[e];
    }
    float lb = 0.f;
    for (int e = 0; e < NEXP; e++)
        lb += (imp[e] / (impSum + 1e-9f)) * (ld[e] / (loadSum + 1e-9f));
    lb *= (float)NEXP;
    float z_loss = 0.001f * (g_z2 / (float)NTOK);
    out[yelems] = 0.01f * lb + z_loss;
    for (int i = yelems + 1; i < out_size; i++) out[i] = 0.f;
}

// ---------------- launch ----------------
extern "C" void kernel_launch(void* const* d_in, const int* in_sizes, int n_in,
                              void* d_out, int out_size) {
    const float* x    = (const float*)d_in[0];
    const float* wr   = (const float*)d_in[1];
    const float* wshg = (const float*)d_in[2];
    const float* wshu = (const float*)d_in[3];
    const float* wshd = (const float*)d_in[4];
    const float* weg  = (const float*)d_in[5];
    const float* weu  = (const float*)d_in[6];
    const float* wed  = (const float*)d_in[7];
    float* out = (float*)d_out;

    // launch order arranged so gemm_gu_kernel sits in the ncu capture window
    router_kernel<<<NTOK, 256>>>(x, wr);           // 1
    reduce_prefix_kernel<<<1, 256>>>();            // 2
    scatter_kernel<<<16, 256>>>();                 // 3

    dim3 gGU(NROWS_ROUTED / BM, NGRP, FDIM / BN);  // (64, 9, 32)
    gemm_gu_kernel<<<gGU, 256>>>(x, weg, wshg, weu, wshu);   // 4 <- profiled slot
    dim3 gD(NROWS_ROUTED / BM, NGRP, HDIM / BN);   // (64, 9, 16)
    gemm_down_kernel<<<gD, 256>>>(wed, wshd);      // 5

    combine_kernel<<<NTOK, 256>>>(out);            // 6
    aux_kernel<<<1, 1>>>(out, out_size);           // 7
}

// round 16
// speedup vs baseline: 1.1571x; 1.1571x over previous
#include <cuda_runtime.h>
#include <cstdint>
#include <math.h>

#define HDIM 1024
#define FDIM 2048
#define NEXP 8
#define NGRP 9
#define NTOK 4096
#define NROWS_ROUTED 8192
#define NROWS_TOTAL 12288

typedef unsigned long long u64;

// ---------------- scratch (static device globals; no allocation) ----------------
__device__ __align__(256) float g_act[(size_t)NROWS_TOTAL * FDIM];  // silu(gate)*up
__device__ __align__(256) float g_y[(size_t)NROWS_TOTAL * HDIM];    // down outputs
__device__ int   g_rowtok[NROWS_TOTAL];
__device__ int   g_tokpos[NTOK * 2];
__device__ float g_tokw[NTOK * 2];
__device__ float g_imp[NEXP];
__device__ int   g_load[NEXP];
__device__ float g_z2;
__device__ int   g_cnt[NEXP];
__device__ int   g_off[NEXP];
__device__ int   g_cur[NEXP];

// ---------------- packed f32x2 helpers ----------------
__device__ __forceinline__ u64 pack2(float x, float y) {
    u64 r; asm("mov.b64 %0, {%1, %2};" : "=l"(r) : "f"(x), "f"(y)); return r;
}
__device__ __forceinline__ u64 ffma2(u64 a, u64 b, u64 c) {
    u64 d; asm("fma.rn.f32x2 %0, %1, %2, %3;" : "=l"(d) : "l"(a), "l"(b), "l"(c)); return d;
}
__device__ __forceinline__ float2 unpack2(u64 v) {
    float2 f; asm("mov.b64 {%0, %1}, %2;" : "=f"(f.x), "=f"(f.y) : "l"(v)); return f;
}

// ---------------- init ----------------
__global__ void init_kernel() {
    int t = threadIdx.x;
    if (t < NEXP) { g_imp[t] = 0.f; g_load[t] = 0; g_cnt[t] = 0; }
    if (t == NEXP) g_z2 = 0.f;
}

// ---------------- router: logits, softmax, top-2, aux stats (proven R13 form) ----------------
__global__ void router_kernel(const float* __restrict__ x, const float* __restrict__ wr) {
    int n = blockIdx.x;
    int tid = threadIdx.x;
    int w = tid >> 5, lane = tid & 31;
    const float* xr = x + (size_t)n * HDIM;
    const float* we = wr + (size_t)w * HDIM;
    float s = 0.f;
    for (int j = lane; j < HDIM; j += 32) s += xr[j] * we[j];
    #pragma unroll
    for (int o = 16; o; o >>= 1) s += __shfl_xor_sync(0xffffffffu, s, o);
    __shared__ float lg[NEXP];
    if (lane == 0) lg[w] = s;
    __syncthreads();
    if (tid == 0) {
        float l[NEXP], p[NEXP];
        float m = -1e30f;
        #pragma unroll
        for (int e = 0; e < NEXP; e++) { l[e] = lg[e]; m = fmaxf(m, l[e]); }
        float se = 0.f;
        #pragma unroll
        for (int e = 0; e < NEXP; e++) { p[e] = expf(l[e] - m); se += p[e]; }
        float inv = 1.f / se;
        #pragma unroll
        for (int e = 0; e < NEXP; e++) { p[e] *= inv; atomicAdd(&g_imp[e], p[e]); }
        float z = m + logf(se);
        atomicAdd(&g_z2, z * z);
        int i1 = 0;
        #pragma unroll
        for (int e = 1; e < NEXP; e++) if (p[e] > p[i1]) i1 = e;
        int i2 = -1;
        #pragma unroll
        for (int e = 0; e < NEXP; e++) {
            if (e == i1) continue;
            if (i2 < 0 || p[e] > p[i2]) i2 = e;
        }
        float denom = p[i1] + p[i2] + 1e-9f;
        g_tokw[n * 2 + 0] = p[i1] / denom;
        g_tokw[n * 2 + 1] = p[i2] / denom;
        atomicAdd(&g_load[i1], 1);
        atomicAdd(&g_cnt[i1], 1);
        atomicAdd(&g_cnt[i2], 1);
        g_tokpos[n * 2 + 0] = i1;
        g_tokpos[n * 2 + 1] = i2;
    }
}

__global__ void prefix_kernel() {
    int o = 0;
    for (int e = 0; e < NEXP; e++) { g_off[e] = o; o += g_cnt[e]; g_cur[e] = 0; }
}

__global__ void scatter_kernel() {
    int n = blockIdx.x * blockDim.x + threadIdx.x;
    if (n < NTOK) {
        #pragma unroll
        for (int k = 0; k < 2; k++) {
            int e = g_tokpos[n * 2 + k];
            int p = g_off[e] + atomicAdd(&g_cur[e], 1);
            g_rowtok[p] = n;
            g_tokpos[n * 2 + k] = p;
        }
        g_rowtok[NROWS_ROUTED + n] = n; // shared-expert group rows
    }
}

// ---------------- grouped GEMMs (FFMA2), duplicated-A smem + B prefetch ----------------
#define BM 128
#define BN 64
#define BK 16

// Fused gate+up: act[r][f] = silu(A[r].Wg[e][f]) * (A[r].Wu[e][f]), K = HDIM
__global__ void __launch_bounds__(256, 2)
gemm_gu_kernel(const float* __restrict__ x,
               const float* __restrict__ weg, const float* __restrict__ wshg,
               const float* __restrict__ weu, const float* __restrict__ wshu) {
    const int g = blockIdx.y;
    int off, cnt;
    if (g < NEXP) { off = g_off[g]; cnt = g_cnt[g]; }
    else          { off = NROWS_ROUTED; cnt = NTOK; }
    const int row0 = blockIdx.x * BM;
    if (row0 >= cnt) return;

    const float* Bg = (g < NEXP) ? (weg + (size_t)g * ((size_t)FDIM * HDIM)) : wshg;
    const float* Bu = (g < NEXP) ? (weu + (size_t)g * ((size_t)FDIM * HDIM)) : wshu;
    const int n0 = blockIdx.z * BN;

    __shared__ u64   Asd[BK][BM + 4];   // duplicated (v,v) pairs
    __shared__ float Bgs[BK][BN + 4];
    __shared__ float Bus[BK][BN + 4];
    __shared__ const float* Arow[BM];

    const int tid = threadIdx.x;
    if (tid < BM) {
        int r = row0 + tid;
        int rc = (r < cnt) ? r : (cnt - 1);
        Arow[tid] = x + (size_t)g_rowtok[off + rc] * HDIM;
    }
    __syncthreads();

    u64 accg[8][2], accu[8][2];
    #pragma unroll
    for (int i = 0; i < 8; i++) { accg[i][0] = accg[i][1] = 0ull; accu[i][0] = accu[i][1] = 0ull; }

    const int tr = tid >> 4, tc = tid & 15;
    const int lm = tid >> 2, lk = tid & 3;      // A-load: row lm, k-quad lk
    const int bn = tid >> 2, bk = tid & 3;      // B-load: col bn, k-quad bk

    const float* aptr0 = Arow[lm]      + lk * 4;
    const float* aptr1 = Arow[lm + 64] + lk * 4;
    const float* bgp = Bg + (size_t)(n0 + bn) * HDIM + bk * 4;
    const float* bup = Bu + (size_t)(n0 + bn) * HDIM + bk * 4;

    // prefetch first B tiles (weights stream from DRAM; x-rows stay L2-hot)
    float4 pg = *(const float4*)(bgp);
    float4 pu = *(const float4*)(bup);

    for (int kt = 0; kt < HDIM; kt += BK) {
        {
            float4 v = *(const float4*)(aptr0 + kt);
            Asd[lk * 4 + 0][lm] = pack2(v.x, v.x);
            Asd[lk * 4 + 1][lm] = pack2(v.y, v.y);
            Asd[lk * 4 + 2][lm] = pack2(v.z, v.z);
            Asd[lk * 4 + 3][lm] = pack2(v.w, v.w);
            float4 w = *(const float4*)(aptr1 + kt);
            Asd[lk * 4 + 0][lm + 64] = pack2(w.x, w.x);
            Asd[lk * 4 + 1][lm + 64] = pack2(w.y, w.y);
            Asd[lk * 4 + 2][lm + 64] = pack2(w.z, w.z);
            Asd[lk * 4 + 3][lm + 64] = pack2(w.w, w.w);
            Bgs[bk * 4 + 0][bn] = pg.x; Bgs[bk * 4 + 1][bn] = pg.y;
            Bgs[bk * 4 + 2][bn] = pg.z; Bgs[bk * 4 + 3][bn] = pg.w;
            Bus[bk * 4 + 0][bn] = pu.x; Bus[bk * 4 + 1][bn] = pu.y;
            Bus[bk * 4 + 2][bn] = pu.z; Bus[bk * 4 + 3][bn] = pu.w;
        }
        __syncthreads();
        if (kt + BK < HDIM) {   // issue next B loads; latency overlapped by compute
            pg = *(const float4*)(bgp + kt + BK);
            pu = *(const float4*)(bup + kt + BK);
        }
        #pragma unroll
        for (int kk = 0; kk < BK; kk++) {
            const u64* ap = &Asd[kk][tr * 8];
            ulonglong2 bg2 = *(const ulonglong2*)&Bgs[kk][tc * 4];
            ulonglong2 bu2 = *(const ulonglong2*)&Bus[kk][tc * 4];
            u64 a2[8];
            #pragma unroll
            for (int i = 0; i < 8; i++) a2[i] = ap[i];
            #pragma unroll
            for (int i = 0; i < 8; i++) {
                accg[i][0] = ffma2(a2[i], bg2.x, accg[i][0]);
                accg[i][1] = ffma2(a2[i], bg2.y, accg[i][1]);
                accu[i][0] = ffma2(a2[i], bu2.x, accu[i][0]);
                accu[i][1] = ffma2(a2[i], bu2.y, accu[i][1]);
            }
        }
        __syncthreads();
    }

    #pragma unroll
    for (int i = 0; i < 8; i++) {
        int r = row0 + tr * 8 + i;
        if (r < cnt) {
            float* o = g_act + (size_t)(off + r) * FDIM + n0 + tc * 4;
            #pragma unroll
            for (int jp = 0; jp < 2; jp++) {
                float2 gg = unpack2(accg[i][jp]);
                float2 uu = unpack2(accu[i][jp]);
                o[jp * 2 + 0] = (gg.x / (1.f + __expf(-gg.x))) * uu.x;
                o[jp * 2 + 1] = (gg.y / (1.f + __expf(-gg.y))) * uu.y;
            }
        }
    }
}

// Down: y[r][h] = act[r] . Wd[e][h], K = FDIM. Duplicated-A smem, A+B prefetch.
__global__ void __launch_bounds__(256, 2)
gemm_down_kernel(const float* __restrict__ wed, const float* __restrict__ wshd) {
    const int g = blockIdx.y;
    int off, cnt;
    if (g < NEXP) { off = g_off[g]; cnt = g_cnt[g]; }
    else          { off = NROWS_ROUTED; cnt = NTOK; }
    const int row0 = blockIdx.x * BM;
    if (row0 >= cnt) return;

    const float* Bp = (g < NEXP) ? (wed + (size_t)g * ((size_t)HDIM * FDIM)) : wshd;
    const int n0 = blockIdx.z * BN;

    __shared__ u64   Asd[BK][BM + 4];
    __shared__ float Bs[BK][BN + 4];

    const int tid = threadIdx.x;
    const int tr = tid >> 4, tc = tid & 15;
    const int lm = tid >> 2, lk = tid & 3;
    const int bn = tid >> 2, bk = tid & 3;

    const int rA  = (row0 + lm      < cnt) ? (row0 + lm)      : (cnt - 1);
    const int rA1 = (row0 + lm + 64 < cnt) ? (row0 + lm + 64) : (cnt - 1);
    const float* a_base0 = g_act + (size_t)(off + rA)  * FDIM + lk * 4;
    const float* a_base1 = g_act + (size_t)(off + rA1) * FDIM + lk * 4;
    const float* b_base  = Bp + (size_t)(n0 + bn) * FDIM + bk * 4;

    u64 acc[8][2];
    #pragma unroll
    for (int i = 0; i < 8; i++) { acc[i][0] = 0ull; acc[i][1] = 0ull; }

    float4 p0 = *(const float4*)(a_base0);
    float4 p1 = *(const float4*)(a_base1);
    float4 pb = *(const float4*)(b_base);

    for (int kt = 0; kt < FDIM; kt += BK) {
        {
            Asd[lk * 4 + 0][lm] = pack2(p0.x, p0.x);
            Asd[lk * 4 + 1][lm] = pack2(p0.y, p0.y);
            Asd[lk * 4 + 2][lm] = pack2(p0.z, p0.z);
            Asd[lk * 4 + 3][lm] = pack2(p0.w, p0.w);
            Asd[lk * 4 + 0][lm + 64] = pack2(p1.x, p1.x);
            Asd[lk * 4 + 1][lm + 64] = pack2(p1.y, p1.y);
            Asd[lk * 4 + 2][lm + 64] = pack2(p1.z, p1.z);
            Asd[lk * 4 + 3][lm + 64] = pack2(p1.w, p1.w);
            Bs[bk * 4 + 0][bn] = pb.x; Bs[bk * 4 + 1][bn] = pb.y;
            Bs[bk * 4 + 2][bn] = pb.z; Bs[bk * 4 + 3][bn] = pb.w;
        }
        __syncthreads();
        if (kt + BK < FDIM) {
            p0 = *(const float4*)(a_base0 + kt + BK);
            p1 = *(const float4*)(a_base1 + kt + BK);
            pb = *(const float4*)(b_base + kt + BK);
        }
        #pragma unroll
        for (int kk = 0; kk < BK; kk++) {
            const u64* ap = &Asd[kk][tr * 8];
            ulonglong2 b2 = *(const ulonglong2*)&Bs[kk][tc * 4];
            u64 a2[8];
            #pragma unroll
            for (int i = 0; i < 8; i++) a2[i] = ap[i];
            #pragma unroll
            for (int i = 0; i < 8; i++) {
                acc[i][0] = ffma2(a2[i], b2.x, acc[i][0]);
                acc[i][1] = ffma2(a2[i], b2.y, acc[i][1]);
            }
        }
        __syncthreads();
    }

    #pragma unroll
    for (int i = 0; i < 8; i++) {
        int r = row0 + tr * 8 + i;
        if (r < cnt) {
            float* o = g_y + (size_t)(off + r) * HDIM + n0 + tc * 4;
            float2 v0 = unpack2(acc[i][0]);
            float2 v1 = unpack2(acc[i][1]);
            o[0] = v0.x; o[1] = v0.y; o[2] = v1.x; o[3] = v1.y;
        }
    }
}

// ---------------- combine: y = shared + w0*e0 + w1*e1 ----------------
__global__ void combine_kernel(float* __restrict__ out) {
    int n = blockIdx.x;
    int p0 = g_tokpos[n * 2], p1 = g_tokpos[n * 2 + 1];
    float w0 = g_tokw[n * 2], w1 = g_tokw[n * 2 + 1];
    const float4* ysh = (const float4*)(g_y + (size_t)(NROWS_ROUTED + n) * HDIM);
    const float4* y0  = (const float4*)(g_y + (size_t)p0 * HDIM);
    const float4* y1  = (const float4*)(g_y + (size_t)p1 * HDIM);
    float4* o = (float4*)(out + (size_t)n * HDIM);
    for (int h = threadIdx.x; h < HDIM / 4; h += blockDim.x) {
        float4 s = ysh[h], a = y0[h], b = y1[h], rr;
        rr.x = s.x + w0 * a.x + w1 * b.x;
        rr.y = s.y + w0 * a.y + w1 * b.y;
        rr.z = s.z + w0 * a.z + w1 * b.z;
        rr.w = s.w + w0 * a.w + w1 * b.w;
        o[h] = rr;
    }
}

// ---------------- aux losses ----------------
__global__ void aux_kernel(float* __restrict__ out, int out_size) {
    const int yelems = NTOK * HDIM;
    if (out_size <= yelems) return;
    float imp[NEXP], ld[NEXP];
    float impSum = 0.f, loadSum = 0.f;
    for (int e = 0; e < NEXP; e++) {
        imp[e] = g_imp[e]; ld[e] = (float)g_load[e];
        impSum += imp[e]; loadSum += ld[e];
    }
    float lb = 0.f;
    for (int e = 0; e < NEXP; e++)
        lb += (imp[e] / (impSum + 1e-9f)) * (ld[e] / (loadSum + 1e-9f));
    lb *= (float)NEXP;
    float z_loss = 0.001f * (g_z2 / (float)NTOK);
    out[yelems] = 0.01f * lb + z_loss;
    for (int i = yelems + 1; i < out_size; i++) out[i] = 0.f;
}

// ---------------- launch (proven R13 graph) ----------------
extern "C" void kernel_launch(void* const* d_in, const int* in_sizes, int n_in,
                              void* d_out, int out_size) {
    const float* x    = (const float*)d_in[0];
    const float* wr   = (const float*)d_in[1];
    const float* wshg = (const float*)d_in[2];
    const float* wshu = (const float*)d_in[3];
    const float* wshd = (const float*)d_in[4];
    const float* weg  = (const float*)d_in[5];
    const float* weu  = (const float*)d_in[6];
    const float* wed  = (const float*)d_in[7];
    float* out = (float*)d_out;

    init_kernel<<<1, 32>>>();
    router_kernel<<<NTOK, 256>>>(x, wr);
    prefix_kernel<<<1, 1>>>();
    scatter_kernel<<<16, 256>>>();

    dim3 gGU(NROWS_ROUTED / BM, NGRP, FDIM / BN);  // (64, 9, 32)
    gemm_gu_kernel<<<gGU, 256>>>(x, weg, wshg, weu, wshu);
    dim3 gD(NROWS_ROUTED / BM, NGRP, HDIM / BN);   // (64, 9, 16)
    gemm_down_kernel<<<gD, 256>>>(wed, wshd);

    combine_kernel<<<NTOK, 256>>>(out);
    aux_kernel<<<1, 1>>>(out, out_size);
}

// round 17
// speedup vs baseline: 1.5600x; 1.3483x over previous
#include <cuda_runtime.h>
#include <cstdint>
#include <math.h>

#define HDIM 1024
#define FDIM 2048
#define NEXP 8
#define NGRP 9
#define NTOK 4096
#define NROWS_ROUTED 8192
#define NROWS_TOTAL 12288

typedef unsigned long long u64;

// ---------------- scratch (static device globals; no allocation) ----------------
__device__ __align__(256) float g_act[(size_t)NROWS_TOTAL * FDIM];  // silu(gate)*up
__device__ __align__(256) float g_y[(size_t)NROWS_TOTAL * HDIM];    // down outputs
__device__ int   g_rowtok[NROWS_TOTAL];
__device__ int   g_tokpos[NTOK * 2];
__device__ float g_tokw[NTOK * 2];
__device__ float g_imp[NEXP];
__device__ int   g_load[NEXP];
__device__ float g_z2;
__device__ int   g_cnt[NEXP];
__device__ int   g_off[NEXP];
__device__ int   g_cur[NEXP];

// ---------------- packed f32x2 helpers ----------------
__device__ __forceinline__ u64 pack2(float x, float y) {
    u64 r; asm("mov.b64 %0, {%1, %2};" : "=l"(r) : "f"(x), "f"(y)); return r;
}
__device__ __forceinline__ u64 ffma2(u64 a, u64 b, u64 c) {
    u64 d; asm("fma.rn.f32x2 %0, %1, %2, %3;" : "=l"(d) : "l"(a), "l"(b), "l"(c)); return d;
}
__device__ __forceinline__ float2 unpack2(u64 v) {
    float2 f; asm("mov.b64 {%0, %1}, %2;" : "=f"(f.x), "=f"(f.y) : "l"(v)); return f;
}

// ---------------- init ----------------
__global__ void init_kernel() {
    int t = threadIdx.x;
    if (t < NEXP) { g_imp[t] = 0.f; g_load[t] = 0; g_cnt[t] = 0; }
    if (t == NEXP) g_z2 = 0.f;
}

// ---------------- router: logits, softmax, top-2, aux stats ----------------
__global__ void router_kernel(const float* __restrict__ x, const float* __restrict__ wr) {
    int n = blockIdx.x;
    int tid = threadIdx.x;
    int w = tid >> 5, lane = tid & 31;
    const float* xr = x + (size_t)n * HDIM;
    const float* we = wr + (size_t)w * HDIM;
    float s = 0.f;
    for (int j = lane; j < HDIM; j += 32) s += xr[j] * we[j];
    #pragma unroll
    for (int o = 16; o; o >>= 1) s += __shfl_xor_sync(0xffffffffu, s, o);
    __shared__ float lg[NEXP];
    if (lane == 0) lg[w] = s;
    __syncthreads();
    if (tid == 0) {
        float l[NEXP], p[NEXP];
        float m = -1e30f;
        #pragma unroll
        for (int e = 0; e < NEXP; e++) { l[e] = lg[e]; m = fmaxf(m, l[e]); }
        float se = 0.f;
        #pragma unroll
        for (int e = 0; e < NEXP; e++) { p[e] = expf(l[e] - m); se += p[e]; }
        float inv = 1.f / se;
        #pragma unroll
        for (int e = 0; e < NEXP; e++) { p[e] *= inv; atomicAdd(&g_imp[e], p[e]); }
        float z = m + logf(se);
        atomicAdd(&g_z2, z * z);
        int i1 = 0;
        #pragma unroll
        for (int e = 1; e < NEXP; e++) if (p[e] > p[i1]) i1 = e;
        int i2 = -1;
        #pragma unroll
        for (int e = 0; e < NEXP; e++) {
            if (e == i1) continue;
            if (i2 < 0 || p[e] > p[i2]) i2 = e;
        }
        float denom = p[i1] + p[i2] + 1e-9f;
        g_tokw[n * 2 + 0] = p[i1] / denom;
        g_tokw[n * 2 + 1] = p[i2] / denom;
        atomicAdd(&g_load[i1], 1);
        atomicAdd(&g_cnt[i1], 1);
        atomicAdd(&g_cnt[i2], 1);
        g_tokpos[n * 2 + 0] = i1;
        g_tokpos[n * 2 + 1] = i2;
    }
}

__global__ void prefix_kernel() {
    int o = 0;
    for (int e = 0; e < NEXP; e++) { g_off[e] = o; o += g_cnt[e]; g_cur[e] = 0; }
}

__global__ void scatter_kernel() {
    int n = blockIdx.x * blockDim.x + threadIdx.x;
    if (n < NTOK) {
        #pragma unroll
        for (int k = 0; k < 2; k++) {
            int e = g_tokpos[n * 2 + k];
            int p = g_off[e] + atomicAdd(&g_cur[e], 1);
            g_rowtok[p] = n;
            g_tokpos[n * 2 + k] = p;
        }
        g_rowtok[NROWS_ROUTED + n] = n; // shared-expert group rows
    }
}

// ---------------- grouped GEMMs (FFMA2), double-buffered smem ----------------
#define BM 128
#define BN 64
#define BK 16

// Fused gate+up: act[r][f] = silu(A[r].Wg[e][f]) * (A[r].Wu[e][f]), K = HDIM
__global__ void __launch_bounds__(256, 2)
gemm_gu_kernel(const float* __restrict__ x,
               const float* __restrict__ weg, const float* __restrict__ wshg,
               const float* __restrict__ weu, const float* __restrict__ wshu) {
    const int g = blockIdx.y;
    int off, cnt;
    if (g < NEXP) { off = g_off[g]; cnt = g_cnt[g]; }
    else          { off = NROWS_ROUTED; cnt = NTOK; }
    const int row0 = blockIdx.x * BM;
    if (row0 >= cnt) return;

    const float* Bg = (g < NEXP) ? (weg + (size_t)g * ((size_t)FDIM * HDIM)) : wshg;
    const float* Bu = (g < NEXP) ? (weu + (size_t)g * ((size_t)FDIM * HDIM)) : wshu;
    const int n0 = blockIdx.z * BN;

    __shared__ float As [2][BK][BM + 4];
    __shared__ float Bgs[2][BK][BN + 4];
    __shared__ float Bus[2][BK][BN + 4];
    __shared__ const float* Arow[BM];

    const int tid = threadIdx.x;
    if (tid < BM) {
        int r = row0 + tid;
        int rc = (r < cnt) ? r : (cnt - 1);
        Arow[tid] = x + (size_t)g_rowtok[off + rc] * HDIM;
    }
    __syncthreads();

    u64 accg[8][2], accu[8][2];
    #pragma unroll
    for (int i = 0; i < 8; i++) { accg[i][0] = accg[i][1] = 0ull; accu[i][0] = accu[i][1] = 0ull; }

    const int tr = tid >> 4, tc = tid & 15;
    const int lm = tid >> 2, lk = tid & 3;      // A-load: row lm(+64), k-quad lk
    const int bn = tid >> 2, bk = tid & 3;      // B-load: col bn, k-quad bk

    const float* aptr0 = Arow[lm]      + lk * 4;
    const float* aptr1 = Arow[lm + 64] + lk * 4;
    const float* bgp = Bg + (size_t)(n0 + bn) * HDIM + bk * 4;
    const float* bup = Bu + (size_t)(n0 + bn) * HDIM + bk * 4;

    const int NCH = HDIM / BK;  // 64

    // prologue: fill stage 0, prefetch regs for stage 1
    float4 ra0 = *(const float4*)(aptr0);
    float4 ra1 = *(const float4*)(aptr1);
    float4 rg  = *(const float4*)(bgp);
    float4 ru  = *(const float4*)(bup);
    {
        As[0][lk * 4 + 0][lm] = ra0.x; As[0][lk * 4 + 1][lm] = ra0.y;
        As[0][lk * 4 + 2][lm] = ra0.z; As[0][lk * 4 + 3][lm] = ra0.w;
        As[0][lk * 4 + 0][lm + 64] = ra1.x; As[0][lk * 4 + 1][lm + 64] = ra1.y;
        As[0][lk * 4 + 2][lm + 64] = ra1.z; As[0][lk * 4 + 3][lm + 64] = ra1.w;
        Bgs[0][bk * 4 + 0][bn] = rg.x; Bgs[0][bk * 4 + 1][bn] = rg.y;
        Bgs[0][bk * 4 + 2][bn] = rg.z; Bgs[0][bk * 4 + 3][bn] = rg.w;
        Bus[0][bk * 4 + 0][bn] = ru.x; Bus[0][bk * 4 + 1][bn] = ru.y;
        Bus[0][bk * 4 + 2][bn] = ru.z; Bus[0][bk * 4 + 3][bn] = ru.w;
    }
    ra0 = *(const float4*)(aptr0 + BK);
    ra1 = *(const float4*)(aptr1 + BK);
    rg  = *(const float4*)(bgp + BK);
    ru  = *(const float4*)(bup + BK);
    __syncthreads();

    for (int c = 0; c < NCH; c++) {
        const int cur = c & 1, nxt = cur ^ 1;
        // stash next stage from prefetched regs (overlaps with compute below)
        if (c + 1 < NCH) {
            As[nxt][lk * 4 + 0][lm] = ra0.x; As[nxt][lk * 4 + 1][lm] = ra0.y;
            As[nxt][lk * 4 + 2][lm] = ra0.z; As[nxt][lk * 4 + 3][lm] = ra0.w;
            As[nxt][lk * 4 + 0][lm + 64] = ra1.x; As[nxt][lk * 4 + 1][lm + 64] = ra1.y;
            As[nxt][lk * 4 + 2][lm + 64] = ra1.z; As[nxt][lk * 4 + 3][lm + 64] = ra1.w;
            Bgs[nxt][bk * 4 + 0][bn] = rg.x; Bgs[nxt][bk * 4 + 1][bn] = rg.y;
            Bgs[nxt][bk * 4 + 2][bn] = rg.z; Bgs[nxt][bk * 4 + 3][bn] = rg.w;
            Bus[nxt][bk * 4 + 0][bn] = ru.x; Bus[nxt][bk * 4 + 1][bn] = ru.y;
            Bus[nxt][bk * 4 + 2][bn] = ru.z; Bus[nxt][bk * 4 + 3][bn] = ru.w;
        }
        if (c + 2 < NCH) {
            int kt = (c + 2) * BK;
            ra0 = *(const float4*)(aptr0 + kt);
            ra1 = *(const float4*)(aptr1 + kt);
            rg  = *(const float4*)(bgp + kt);
            ru  = *(const float4*)(bup + kt);
        }
        #pragma unroll
        for (int kk = 0; kk < BK; kk++) {
            float4 a0 = *(const float4*)&As[cur][kk][tr * 8];
            float4 a1 = *(const float4*)&As[cur][kk][tr * 8 + 4];
            ulonglong2 bg2 = *(const ulonglong2*)&Bgs[cur][kk][tc * 4];
            ulonglong2 bu2 = *(const ulonglong2*)&Bus[cur][kk][tc * 4];
            float a[8] = {a0.x, a0.y, a0.z, a0.w, a1.x, a1.y, a1.z, a1.w};
            #pragma unroll
            for (int i = 0; i < 8; i++) {
                u64 t = pack2(a[i], a[i]);
                accg[i][0] = ffma2(t, bg2.x, accg[i][0]);
                accg[i][1] = ffma2(t, bg2.y, accg[i][1]);
                accu[i][0] = ffma2(t, bu2.x, accu[i][0]);
                accu[i][1] = ffma2(t, bu2.y, accu[i][1]);
            }
        }
        __syncthreads();
    }

    #pragma unroll
    for (int i = 0; i < 8; i++) {
        int r = row0 + tr * 8 + i;
        if (r < cnt) {
            float* o = g_act + (size_t)(off + r) * FDIM + n0 + tc * 4;
            #pragma unroll
            for (int jp = 0; jp < 2; jp++) {
                float2 gg = unpack2(accg[i][jp]);
                float2 uu = unpack2(accu[i][jp]);
                o[jp * 2 + 0] = (gg.x / (1.f + __expf(-gg.x))) * uu.x;
                o[jp * 2 + 1] = (gg.y / (1.f + __expf(-gg.y))) * uu.y;
            }
        }
    }
}

// Down: y[r][h] = act[r] . Wd[e][h], K = FDIM. Double-buffered.
__global__ void __launch_bounds__(256, 2)
gemm_down_kernel(const float* __restrict__ wed, const float* __restrict__ wshd) {
    const int g = blockIdx.y;
    int off, cnt;
    if (g < NEXP) { off = g_off[g]; cnt = g_cnt[g]; }
    else          { off = NROWS_ROUTED; cnt = NTOK; }
    const int row0 = blockIdx.x * BM;
    if (row0 >= cnt) return;

    const float* Bp = (g < NEXP) ? (wed + (size_t)g * ((size_t)HDIM * FDIM)) : wshd;
    const int n0 = blockIdx.z * BN;

    __shared__ float As[2][BK][BM + 4];
    __shared__ float Bs[2][BK][BN + 4];

    const int tid = threadIdx.x;
    const int tr = tid >> 4, tc = tid & 15;
    const int lm = tid >> 2, lk = tid & 3;
    const int bn = tid >> 2, bk = tid & 3;

    const int rA  = (row0 + lm      < cnt) ? (row0 + lm)      : (cnt - 1);
    const int rA1 = (row0 + lm + 64 < cnt) ? (row0 + lm + 64) : (cnt - 1);
    const float* a_base0 = g_act + (size_t)(off + rA)  * FDIM + lk * 4;
    const float* a_base1 = g_act + (size_t)(off + rA1) * FDIM + lk * 4;
    const float* b_base  = Bp + (size_t)(n0 + bn) * FDIM + bk * 4;

    u64 acc[8][2];
    #pragma unroll
    for (int i = 0; i < 8; i++) { acc[i][0] = 0ull; acc[i][1] = 0ull; }

    const int NCH = FDIM / BK;  // 128

    float4 p0 = *(const float4*)(a_base0);
    float4 p1 = *(const float4*)(a_base1);
    float4 pb = *(const float4*)(b_base);
    {
        As[0][lk * 4 + 0][lm] = p0.x; As[0][lk * 4 + 1][lm] = p0.y;
        As[0][lk * 4 + 2][lm] = p0.z; As[0][lk * 4 + 3][lm] = p0.w;
        As[0][lk * 4 + 0][lm + 64] = p1.x; As[0][lk * 4 + 1][lm + 64] = p1.y;
        As[0][lk * 4 + 2][lm + 64] = p1.z; As[0][lk * 4 + 3][lm + 64] = p1.w;
        Bs[0][bk * 4 + 0][bn] = pb.x; Bs[0][bk * 4 + 1][bn] = pb.y;
        Bs[0][bk * 4 + 2][bn] = pb.z; Bs[0][bk * 4 + 3][bn] = pb.w;
    }
    p0 = *(const float4*)(a_base0 + BK);
    p1 = *(const float4*)(a_base1 + BK);
    pb = *(const float4*)(b_base + BK);
    __syncthreads();

    for (int c = 0; c < NCH; c++) {
        const int cur = c & 1, nxt = cur ^ 1;
        if (c + 1 < NCH) {
            As[nxt][lk * 4 + 0][lm] = p0.x; As[nxt][lk * 4 + 1][lm] = p0.y;
            As[nxt][lk * 4 + 2][lm] = p0.z; As[nxt][lk * 4 + 3][lm] = p0.w;
            As[nxt][lk * 4 + 0][lm + 64] = p1.x; As[nxt][lk * 4 + 1][lm + 64] = p1.y;
            As[nxt][lk * 4 + 2][lm + 64] = p1.z; As[nxt][lk * 4 + 3][lm + 64] = p1.w;
            Bs[nxt][bk * 4 + 0][bn] = pb.x; Bs[nxt][bk * 4 + 1][bn] = pb.y;
            Bs[nxt][bk * 4 + 2][bn] = pb.z; Bs[nxt][bk * 4 + 3][bn] = pb.w;
        }
        if (c + 2 < NCH) {
            int kt = (c + 2) * BK;
            p0 = *(const float4*)(a_base0 + kt);
            p1 = *(const float4*)(a_base1 + kt);
            pb = *(const float4*)(b_base + kt);
        }
        #pragma unroll
        for (int kk = 0; kk < BK; kk++) {
            float4 a0 = *(const float4*)&As[cur][kk][tr * 8];
            float4 a1 = *(const float4*)&As[cur][kk][tr * 8 + 4];
            ulonglong2 b2 = *(const ulonglong2*)&Bs[cur][kk][tc * 4];
            float a[8] = {a0.x, a0.y, a0.z, a0.w, a1.x, a1.y, a1.z, a1.w};
            #pragma unroll
            for (int i = 0; i < 8; i++) {
                u64 t = pack2(a[i], a[i]);
                acc[i][0] = ffma2(t, b2.x, acc[i][0]);
                acc[i][1] = ffma2(t, b2.y, acc[i][1]);
            }
        }
        __syncthreads();
    }

    #pragma unroll
    for (int i = 0; i < 8; i++) {
        int r = row0 + tr * 8 + i;
        if (r < cnt) {
            float* o = g_y + (size_t)(off + r) * HDIM + n0 + tc * 4;
            float2 v0 = unpack2(acc[i][0]);
            float2 v1 = unpack2(acc[i][1]);
            o[0] = v0.x; o[1] = v0.y; o[2] = v1.x; o[3] = v1.y;
        }
    }
}

// ---------------- combine: y = shared + w0*e0 + w1*e1 ----------------
__global__ void combine_kernel(float* __restrict__ out) {
    int n = blockIdx.x;
    int p0 = g_tokpos[n * 2], p1 = g_tokpos[n * 2 + 1];
    float w0 = g_tokw[n * 2], w1 = g_tokw[n * 2 + 1];
    const float4* ysh = (const float4*)(g_y + (size_t)(NROWS_ROUTED + n) * HDIM);
    const float4* y0  = (const float4*)(g_y + (size_t)p0 * HDIM);
    const float4* y1  = (const float4*)(g_y + (size_t)p1 * HDIM);
    float4* o = (float4*)(out + (size_t)n * HDIM);
    for (int h = threadIdx.x; h < HDIM / 4; h += blockDim.x) {
        float4 s = ysh[h], a = y0[h], b = y1[h], rr;
        rr.x = s.x + w0 * a.x + w1 * b.x;
        rr.y = s.y + w0 * a.y + w1 * b.y;
        rr.z = s.z + w0 * a.z + w1 * b.z;
        rr.w = s.w + w0 * a.w + w1 * b.w;
        o[h] = rr;
    }
}

// ---------------- aux losses ----------------
__global__ void aux_kernel(float* __restrict__ out, int out_size) {
    const int yelems = NTOK * HDIM;
    if (out_size <= yelems) return;
    float imp[NEXP], ld[NEXP];
    float impSum = 0.f, loadSum = 0.f;
    for (int e = 0; e < NEXP; e++) {
        imp[e] = g_imp[e]; ld[e] = (float)g_load[e];
        impSum += imp[e]; loadSum += ld[e];
    }
    float lb = 0.f;
    for (int e = 0; e < NEXP; e++)
        lb += (imp[e] / (impSum + 1e-9f)) * (ld[e] / (loadSum + 1e-9f));
    lb *= (float)NEXP;
    float z_loss = 0.001f * (g_z2 / (float)NTOK);
    out[yelems] = 0.01f * lb + z_loss;
    for (int i = yelems + 1; i < out_size; i++) out[i] = 0.f;
}

// ---------------- launch (proven R13 graph) ----------------
extern "C" void kernel_launch(void* const* d_in, const int* in_sizes, int n_in,
                              void* d_out, int out_size) {
    const float* x    = (const float*)d_in[0];
    const float* wr   = (const float*)d_in[1];
    const float* wshg = (const float*)d_in[2];
    const float* wshu = (const float*)d_in[3];
    const float* wshd = (const float*)d_in[4];
    const float* weg  = (const float*)d_in[5];
    const float* weu  = (const float*)d_in[6];
    const float* wed  = (const float*)d_in[7];
    float* out = (float*)d_out;

    init_kernel<<<1, 32>>>();
    router_kernel<<<NTOK, 256>>>(x, wr);
    prefix_kernel<<<1, 1>>>();
    scatter_kernel<<<16, 256>>>();

    dim3 gGU(NROWS_ROUTED / BM, NGRP, FDIM / BN);  // (64, 9, 32)
    gemm_gu_kernel<<<gGU, 256>>>(x, weg, wshg, weu, wshu);
    dim3 gD(NROWS_ROUTED / BM, NGRP, HDIM / BN);   // (64, 9, 16)
    gemm_down_kernel<<<gD, 256>>>(wed, wshd);

    combine_kernel<<<NTOK, 256>>>(out);
    aux_kernel<<<1, 1>>>(out, out_size);
}